// round 1
// baseline (speedup 1.0000x reference)
#include <cuda_runtime.h>
#include <cuda_bf16.h>
#include <math.h>

// Zero the scalar output (d_out is poisoned to 0xAA by the harness).
__global__ void dist_zero_kernel(float* __restrict__ out) {
    if (threadIdx.x == 0 && blockIdx.x == 0) out[0] = 0.0f;
}

// Fused distance + mean reduction.
// preds/targets are [N,2] float32, viewed as float4 (2 points per load).
__global__ void __launch_bounds__(256, 8)
DIST_loss_49331994362453_kernel(const float4* __restrict__ preds,
                                const float4* __restrict__ targets,
                                float* __restrict__ out,
                                int n4, float inv_np1) {
    float acc = 0.0f;
    const int stride = gridDim.x * blockDim.x;
    for (int i = blockIdx.x * blockDim.x + threadIdx.x; i < n4; i += stride) {
        float4 a = preds[i];
        float4 b = targets[i];
        float dx0 = a.x - b.x;
        float dy0 = a.y - b.y;
        float dx1 = a.z - b.z;
        float dy1 = a.w - b.w;
        acc += sqrtf(fmaf(dx0, dx0, dy0 * dy0));
        acc += sqrtf(fmaf(dx1, dx1, dy1 * dy1));
    }

    // Warp reduction
    #pragma unroll
    for (int o = 16; o > 0; o >>= 1)
        acc += __shfl_down_sync(0xffffffffu, acc, o);

    __shared__ float warpsum[8];  // 256 threads = 8 warps
    const int lane = threadIdx.x & 31;
    const int wid  = threadIdx.x >> 5;
    if (lane == 0) warpsum[wid] = acc;
    __syncthreads();

    if (wid == 0) {
        acc = (lane < 8) ? warpsum[lane] : 0.0f;
        #pragma unroll
        for (int o = 4; o > 0; o >>= 1)
            acc += __shfl_down_sync(0xffffffffu, acc, o);
        if (lane == 0)
            atomicAdd(out, acc * inv_np1);  // fold the /(N+1) in here
    }
}

extern "C" void kernel_launch(void* const* d_in, const int* in_sizes, int n_in,
                              void* d_out, int out_size) {
    const float4* preds   = (const float4*)d_in[0];
    const float4* targets = (const float4*)d_in[1];
    float* out = (float*)d_out;

    const int total_elems = in_sizes[0];      // N*2 floats
    const int n_points    = total_elems / 2;  // N
    const int n4          = total_elems / 4;  // float4 count (2 points each)
    const float inv_np1   = 1.0f / (float)(n_points + 1);

    dist_zero_kernel<<<1, 32>>>(out);

    const int threads = 256;
    int blocks = (n4 + threads - 1) / threads;
    const int max_blocks = 148 * 16;  // 2368: ~14 iters/thread at N=16M
    if (blocks > max_blocks) blocks = max_blocks;

    DIST_loss_49331994362453_kernel<<<blocks, threads>>>(preds, targets, out,
                                                         n4, inv_np1);
}

// round 3
// speedup vs baseline: 1.0051x; 1.0051x over previous
#include <cuda_runtime.h>
#include <cuda_bf16.h>
#include <math.h>

// Last-block-finalize scratch. Zero-initialized at load; the finalizing block
// resets g_partial via atomicExch and the counter auto-wraps via atomicInc,
// so every graph replay sees the same initial state. No extra kernel needed.
__device__ float        g_partial;  // = 0
__device__ unsigned int g_count;    // = 0

__device__ __forceinline__ float4 ldcs4(const float4* p) {
    return __ldcs(p);
}

// Fused distance + mean reduction, unroll x4 for deep MLP (8 outstanding
// LDG.128 per thread before any dependent math).
__global__ void __launch_bounds__(256, 5)
DIST_loss_49331994362453_kernel(const float4* __restrict__ preds,
                                const float4* __restrict__ targets,
                                float* __restrict__ out,
                                int n4, float inv_np1) {
    const int stride = gridDim.x * blockDim.x;
    int i = blockIdx.x * blockDim.x + threadIdx.x;

    float acc0 = 0.0f, acc1 = 0.0f, acc2 = 0.0f, acc3 = 0.0f;

    // Main unrolled loop: 8 independent 16B loads batched up front.
    for (; i + 3 * stride < n4; i += 4 * stride) {
        float4 a0 = ldcs4(preds   + i);
        float4 a1 = ldcs4(preds   + i + stride);
        float4 a2 = ldcs4(preds   + i + 2 * stride);
        float4 a3 = ldcs4(preds   + i + 3 * stride);
        float4 b0 = ldcs4(targets + i);
        float4 b1 = ldcs4(targets + i + stride);
        float4 b2 = ldcs4(targets + i + 2 * stride);
        float4 b3 = ldcs4(targets + i + 3 * stride);

        float dx, dy;
        dx = a0.x - b0.x; dy = a0.y - b0.y; acc0 += sqrtf(fmaf(dx, dx, dy * dy));
        dx = a0.z - b0.z; dy = a0.w - b0.w; acc0 += sqrtf(fmaf(dx, dx, dy * dy));
        dx = a1.x - b1.x; dy = a1.y - b1.y; acc1 += sqrtf(fmaf(dx, dx, dy * dy));
        dx = a1.z - b1.z; dy = a1.w - b1.w; acc1 += sqrtf(fmaf(dx, dx, dy * dy));
        dx = a2.x - b2.x; dy = a2.y - b2.y; acc2 += sqrtf(fmaf(dx, dx, dy * dy));
        dx = a2.z - b2.z; dy = a2.w - b2.w; acc2 += sqrtf(fmaf(dx, dx, dy * dy));
        dx = a3.x - b3.x; dy = a3.y - b3.y; acc3 += sqrtf(fmaf(dx, dx, dy * dy));
        dx = a3.z - b3.z; dy = a3.w - b3.w; acc3 += sqrtf(fmaf(dx, dx, dy * dy));
    }
    // Tail
    for (; i < n4; i += stride) {
        float4 a = ldcs4(preds + i);
        float4 b = ldcs4(targets + i);
        float dx, dy;
        dx = a.x - b.x; dy = a.y - b.y; acc0 += sqrtf(fmaf(dx, dx, dy * dy));
        dx = a.z - b.z; dy = a.w - b.w; acc0 += sqrtf(fmaf(dx, dx, dy * dy));
    }

    float acc = (acc0 + acc1) + (acc2 + acc3);

    // Warp reduction
    #pragma unroll
    for (int o = 16; o > 0; o >>= 1)
        acc += __shfl_down_sync(0xffffffffu, acc, o);

    __shared__ float warpsum[8];  // 256 threads = 8 warps
    const int lane = threadIdx.x & 31;
    const int wid  = threadIdx.x >> 5;
    if (lane == 0) warpsum[wid] = acc;
    __syncthreads();

    if (wid == 0) {
        acc = (lane < 8) ? warpsum[lane] : 0.0f;
        #pragma unroll
        for (int o = 4; o > 0; o >>= 1)
            acc += __shfl_down_sync(0xffffffffu, acc, o);

        if (lane == 0) {
            atomicAdd(&g_partial, acc);
            __threadfence();
            // atomicInc wraps to 0 at gridDim.x-1 -> counter self-resets.
            unsigned int ticket = atomicInc(&g_count, gridDim.x - 1);
            if (ticket == gridDim.x - 1) {
                // Last block: drain + self-reset the accumulator, write result.
                float total = atomicExch(&g_partial, 0.0f);
                out[0] = total * inv_np1;
            }
        }
    }
}

extern "C" void kernel_launch(void* const* d_in, const int* in_sizes, int n_in,
                              void* d_out, int out_size) {
    const float4* preds   = (const float4*)d_in[0];
    const float4* targets = (const float4*)d_in[1];
    float* out = (float*)d_out;

    const int total_elems = in_sizes[0];      // N*2 floats
    const int n_points    = total_elems / 2;  // N
    const int n4          = total_elems / 4;  // float4 count (2 points each)
    const float inv_np1   = 1.0f / (float)(n_points + 1);

    const int threads = 256;
    int blocks = 148 * 5;  // one exact wave at occupancy 5 (launch_bounds 256,5)
    int max_needed = (n4 + threads - 1) / threads;
    if (blocks > max_needed) blocks = max_needed;

    DIST_loss_49331994362453_kernel<<<blocks, threads>>>(preds, targets, out,
                                                         n4, inv_np1);
}